// round 16
// baseline (speedup 1.0000x reference)
#include <cuda_runtime.h>
#include <cuda_bf16.h>

#define POOL 7
#define NCELL 49
#define C 256
#define NBKT 128     // batch(1b) x level(2b) x yq(2b) x xq(2b)
#define MAXBOX 4096

__device__ int g_perm[MAXBOX];

// One-block classify sort: groups boxes by (batch, level, quantized center).
// Parallel scan -> ~1-2 us total.
__global__ __launch_bounds__(256) void sort_boxes_kernel(
    const float* __restrict__ boxes,
    const float* __restrict__ meta,
    int N, int BN)
{
    __shared__ int s_cnt[NBKT];
    __shared__ int s_scan[2][NBKT];
    __shared__ int s_cur[NBKT];
    __shared__ unsigned char s_key[MAXBOX];

    const int tid = threadIdx.x;
    const int n = min(BN, MAXBOX);

    if (tid < NBKT) { s_cnt[tid] = 0; s_cur[tid] = 0; }
    __syncthreads();

    const float area  = meta[4] * meta[5];
    const float denom = 224.0f / sqrtf(area);

    for (int i = tid; i < n; i += 256) {
        const float by1 = boxes[i * 4 + 0];
        const float bx1 = boxes[i * 4 + 1];
        const float by2 = boxes[i * 4 + 2];
        const float bx2 = boxes[i * 4 + 3];

        const float lvl = log2f(sqrtf((by2 - by1) * (bx2 - bx1)) / denom);
        float lv = 4.0f + rintf(lvl);
        lv = fminf(fmaxf(lv, 2.0f), 5.0f);
        const int level = (int)lv;
        const int batch = i / N;

        const int yq = min(max((int)((by1 + by2) * 2.0f), 0), 3);  // 0.5*(y1+y2)*4
        const int xq = min(max((int)((bx1 + bx2) * 2.0f), 0), 3);

        const int key = ((((batch & 1) * 4 + (level - 2)) * 4 + yq) * 4 + xq) & (NBKT - 1);
        s_key[i] = (unsigned char)key;
        atomicAdd(&s_cnt[key], 1);
    }
    __syncthreads();

    // Hillis-Steele exclusive scan over 128 buckets (threads 0..127)
    if (tid < NBKT)
        s_scan[0][tid] = (tid > 0) ? s_cnt[tid - 1] : 0;   // shift for exclusive
    __syncthreads();
    int src = 0;
    for (int d = 1; d < NBKT; d <<= 1) {
        if (tid < NBKT)
            s_scan[src ^ 1][tid] = s_scan[src][tid] +
                                   ((tid >= d) ? s_scan[src][tid - d] : 0);
        src ^= 1;
        __syncthreads();
    }

    for (int i = tid; i < n; i += 256) {
        const int key = s_key[i];
        const int pos = s_scan[src][key] + atomicAdd(&s_cur[key], 1);
        g_perm[pos] = i;   // permutation only; per-box outputs are independent
    }
    for (int i = n + tid; i < BN && i < MAXBOX; i += 256) g_perm[i] = i;
}

// Each block processes 2 CONSECUTIVE SORTED boxes sequentially: same level +
// neighborhood -> box 2's corner lines hit in L1 (per-SM), cutting L2 read bytes.
__global__ __launch_bounds__(256) void roi_align_kernel(
    const float* __restrict__ boxes,
    const float* __restrict__ meta,
    const float* __restrict__ f2,
    const float* __restrict__ f3,
    const float* __restrict__ f4,
    const float* __restrict__ f5,
    float* __restrict__ out,
    int N, int BN)
{
    const int tid = threadIdx.x;

    __shared__ int4   s_off[2][NCELL];
    __shared__ float2 s_frac[2][NCELL];    // {fx, fy}

    const float area  = meta[4] * meta[5];
    const float denom = 224.0f / sqrtf(area);

    const int ch = (tid & 63) * 4;         // channel offset (64 lanes x float4 = C)
    const int g  = tid >> 6;               // cell group 0..3

    #pragma unroll 1
    for (int j = 0; j < 2; j++) {
        const int sidx = blockIdx.x * 2 + j;
        if (sidx >= BN) break;
        const int box_id = g_perm[sidx];
        const int batch  = box_id / N;

        const float by1 = boxes[box_id * 4 + 0];
        const float bx1 = boxes[box_id * 4 + 1];
        const float by2 = boxes[box_id * 4 + 2];
        const float bx2 = boxes[box_id * 4 + 3];

        const float lvl = log2f(sqrtf((by2 - by1) * (bx2 - bx1)) / denom);
        float lv = 4.0f + rintf(lvl);      // rintf = round-half-even = jnp.round
        lv = fminf(fmaxf(lv, 2.0f), 5.0f);
        const int level = (int)lv;

        int Hs;
        const float* f;
        if (level == 2)      { Hs = 256; f = f2; }
        else if (level == 3) { Hs = 128; f = f3; }
        else if (level == 4) { Hs = 64;  f = f4; }
        else                 { Hs = 32;  f = f5; }
        const int Ws = Hs;
        const float* base = f + (size_t)batch * Hs * Ws * C;

        if (tid < NCELL) {
            const int py = tid / POOL;
            const int px = tid - py * POOL;

            const float ys = by1 * (float)(Hs - 1)
                           + (float)py * ((by2 - by1) * (float)(Hs - 1) / (float)(POOL - 1));
            const float xs = bx1 * (float)(Ws - 1)
                           + (float)px * ((bx2 - bx1) * (float)(Ws - 1) / (float)(POOL - 1));

            const float y0f = floorf(ys);
            const float x0f = floorf(xs);
            int y0 = min(max((int)y0f, 0), Hs - 1);
            int x0 = min(max((int)x0f, 0), Ws - 1);
            const int y1 = min(y0 + 1, Hs - 1);
            const int x1 = min(x0 + 1, Ws - 1);

            s_off[j][tid]  = make_int4((y0 * Ws + x0) * C, (y0 * Ws + x1) * C,
                                       (y1 * Ws + x0) * C, (y1 * Ws + x1) * C);
            s_frac[j][tid] = make_float2(xs - x0f, ys - y0f);
        }
        __syncthreads();

        const float* bch   = base + ch;
        float*       obase = out + (size_t)box_id * (NCELL * C) + ch;

        auto do_cell = [&](int cell) {
            const int4   off = s_off[j][cell];
            const float2 fr  = s_frac[j][cell];

            const float4 tl = *(const float4*)(bch + off.x);
            const float4 tr = *(const float4*)(bch + off.y);
            const float4 bl = *(const float4*)(bch + off.z);
            const float4 br = *(const float4*)(bch + off.w);

            float4 o;
            {
                const float top = tl.x + (tr.x - tl.x) * fr.x;
                const float bot = bl.x + (br.x - bl.x) * fr.x;
                o.x = top + (bot - top) * fr.y;
            }
            {
                const float top = tl.y + (tr.y - tl.y) * fr.x;
                const float bot = bl.y + (br.y - bl.y) * fr.x;
                o.y = top + (bot - top) * fr.y;
            }
            {
                const float top = tl.z + (tr.z - tl.z) * fr.x;
                const float bot = bl.z + (br.z - bl.z) * fr.x;
                o.z = top + (bot - top) * fr.y;
            }
            {
                const float top = tl.w + (tr.w - tl.w) * fr.x;
                const float bot = bl.w + (br.w - bl.w) * fr.x;
                o.w = top + (bot - top) * fr.y;
            }
            __stwt((float4*)(obase + (size_t)cell * C), o);
        };

        #pragma unroll 1
        for (int k = 0; k < 6; k++) {
            const int c0 = g + 8 * k;
            do_cell(c0);
            do_cell(c0 + 4);
        }
        if (g == 0) do_cell(48);
        // descriptor buffers are per-j, so no barrier needed before next j's build
    }
}

extern "C" void kernel_launch(void* const* d_in, const int* in_sizes, int n_in,
                              void* d_out, int out_size) {
    const float* boxes = (const float*)d_in[0];
    const float* meta  = (const float*)d_in[1];
    const float* f2    = (const float*)d_in[2];
    const float* f3    = (const float*)d_in[3];
    const float* f4    = (const float*)d_in[4];
    const float* f5    = (const float*)d_in[5];
    float* out = (float*)d_out;

    const int BN = in_sizes[0] / 4;                    // total boxes = B*N
    const int B  = in_sizes[2] / (256 * 256 * 256);    // feat2 = B*256*256*C
    const int N  = BN / B;

    sort_boxes_kernel<<<1, 256>>>(boxes, meta, N, BN);

    const int nblocks = (BN + 1) / 2;
    roi_align_kernel<<<nblocks, 256>>>(boxes, meta, f2, f3, f4, f5, out, N, BN);
}

// round 17
// speedup vs baseline: 1.0608x; 1.0608x over previous
#include <cuda_runtime.h>
#include <cuda_bf16.h>

#define POOL 7
#define NCELL 49
#define C 256

__global__ __launch_bounds__(256) void roi_align_kernel(
    const float* __restrict__ boxes,
    const float* __restrict__ meta,
    const float* __restrict__ f2,
    const float* __restrict__ f3,
    const float* __restrict__ f4,
    const float* __restrict__ f5,
    float* __restrict__ out,
    int N)
{
    const int box_id = blockIdx.x;         // 0 .. B*N-1
    const int batch  = box_id / N;
    const int tid    = threadIdx.x;

    __shared__ int4   s_off[NCELL];        // corner element offsets
    __shared__ float2 s_frac[NCELL];       // {fx, fy}

    // --- per-box scalars (redundant per thread; cheap) ---
    const float by1 = boxes[box_id * 4 + 0];
    const float bx1 = boxes[box_id * 4 + 1];
    const float by2 = boxes[box_id * 4 + 2];
    const float bx2 = boxes[box_id * 4 + 3];

    const float area = meta[4] * meta[5];
    const float lvl  = log2f(sqrtf((by2 - by1) * (bx2 - bx1)) / (224.0f / sqrtf(area)));
    float lv = 4.0f + rintf(lvl);          // rintf = round-half-even = jnp.round
    lv = fminf(fmaxf(lv, 2.0f), 5.0f);
    const int level = (int)lv;

    int Hs;
    const float* f;
    if (level == 2)      { Hs = 256; f = f2; }
    else if (level == 3) { Hs = 128; f = f3; }
    else if (level == 4) { Hs = 64;  f = f4; }
    else                 { Hs = 32;  f = f5; }
    const int Ws = Hs;
    const float* base = f + (size_t)batch * Hs * Ws * C;

    // --- build the 49 cell descriptors (one thread per cell) ---
    if (tid < NCELL) {
        const int py = tid / POOL;
        const int px = tid - py * POOL;

        const float ys = by1 * (float)(Hs - 1)
                       + (float)py * ((by2 - by1) * (float)(Hs - 1) / (float)(POOL - 1));
        const float xs = bx1 * (float)(Ws - 1)
                       + (float)px * ((bx2 - bx1) * (float)(Ws - 1) / (float)(POOL - 1));

        const float y0f = floorf(ys);
        const float x0f = floorf(xs);
        int y0 = min(max((int)y0f, 0), Hs - 1);
        int x0 = min(max((int)x0f, 0), Ws - 1);
        const int y1 = min(y0 + 1, Hs - 1);
        const int x1 = min(x0 + 1, Ws - 1);

        s_off[tid]  = make_int4((y0 * Ws + x0) * C, (y0 * Ws + x1) * C,
                                (y1 * Ws + x0) * C, (y1 * Ws + x1) * C);
        s_frac[tid] = make_float2(xs - x0f, ys - y0f);
    }
    __syncthreads();

    // --- main loop: 64 lanes x float4 cover C=256; 4 cell-groups ---
    const int ch = (tid & 63) * 4;         // channel offset
    const int g  = tid >> 6;               // cell group 0..3
    const float* bch   = base + ch;
    float*       obase = out + (size_t)box_id * (NCELL * C) + ch;

    // register-free latency hiding: warm L1 for a cell's 4 corner lines
    auto prefetch_cell = [&](int cell) {
        const int4 off = s_off[cell];
        asm volatile("prefetch.global.L1 [%0];" :: "l"(bch + off.x));
        asm volatile("prefetch.global.L1 [%0];" :: "l"(bch + off.y));
        asm volatile("prefetch.global.L1 [%0];" :: "l"(bch + off.z));
        asm volatile("prefetch.global.L1 [%0];" :: "l"(bch + off.w));
    };

    auto do_cell = [&](int cell) {
        const int4   off = s_off[cell];
        const float2 fr  = s_frac[cell];

        const float4 tl = *(const float4*)(bch + off.x);
        const float4 tr = *(const float4*)(bch + off.y);
        const float4 bl = *(const float4*)(bch + off.z);
        const float4 br = *(const float4*)(bch + off.w);

        float4 o;
        {
            const float top = tl.x + (tr.x - tl.x) * fr.x;
            const float bot = bl.x + (br.x - bl.x) * fr.x;
            o.x = top + (bot - top) * fr.y;
        }
        {
            const float top = tl.y + (tr.y - tl.y) * fr.x;
            const float bot = bl.y + (br.y - bl.y) * fr.x;
            o.y = top + (bot - top) * fr.y;
        }
        {
            const float top = tl.z + (tr.z - tl.z) * fr.x;
            const float bot = bl.z + (br.z - bl.z) * fr.x;
            o.z = top + (bot - top) * fr.y;
        }
        {
            const float top = tl.w + (tr.w - tl.w) * fr.x;
            const float bot = bl.w + (br.w - bl.w) * fr.x;
            o.w = top + (bot - top) * fr.y;
        }
        __stwt((float4*)(obase + (size_t)cell * C), o);  // streaming store
    };

    // prime the pipe: prefetch iteration 0's pair for this group
    prefetch_cell(g);
    prefetch_cell(g + 4);

    // groups 0..3 cover cells g+8k and g+4+8k; prefetch next iter before
    // consuming the current one so real loads land on warm L1 lines.
    #pragma unroll 1
    for (int k = 0; k < 6; k++) {
        const int c0 = g + 8 * k;
        if (k < 5) {
            prefetch_cell(c0 + 8);
            prefetch_cell(c0 + 12);
        } else if (g == 0) {
            prefetch_cell(48);
        }
        do_cell(c0);
        do_cell(c0 + 4);
    }
    if (g == 0) do_cell(48);
}

extern "C" void kernel_launch(void* const* d_in, const int* in_sizes, int n_in,
                              void* d_out, int out_size) {
    const float* boxes = (const float*)d_in[0];
    const float* meta  = (const float*)d_in[1];
    const float* f2    = (const float*)d_in[2];
    const float* f3    = (const float*)d_in[3];
    const float* f4    = (const float*)d_in[4];
    const float* f5    = (const float*)d_in[5];
    float* out = (float*)d_out;

    const int BN = in_sizes[0] / 4;                    // total boxes = B*N
    const int B  = in_sizes[2] / (256 * 256 * 256);    // feat2 = B*256*256*C
    const int N  = BN / B;

    roi_align_kernel<<<BN, 256>>>(boxes, meta, f2, f3, f4, f5, out, N);
}